// round 16
// baseline (speedup 1.0000x reference)
#include <cuda_runtime.h>
#include <math.h>

// Problem geometry (fixed by reference): T=1e6, D=82, 256 groups
#define D        82
#define NGROUP   256
#define TPB      96           // threads per block == rows per tile
#define ROWS     96
#define SLOTS    21           // weighted partials per row
#define BLOCKS_PER_SM 12
#define MAX_GRID (148 * BLOCKS_PER_SM)   // 1776

// Per-group stats, one 128-byte line per group (per-address L2 serialization
// spread across 256 lines / LTS slices). float slots within the line:
//   [0]=n [1]=Sx [2]=Sy [3]=Sxx   (v4 red)   [4]=Syy [5]=Sxy (v2 red)
// Zero-initialized at module load; last block resets after use so every
// launch / graph replay starts from identical state.
__device__ __align__(128) float g_statsPad[NGROUP * 32];
__device__ unsigned g_ticket;

// Fused persistent kernel: weighted-partial double-buffered staging; group
// stats via TWO fire-and-forget vector global reductions per row
// (RED.ADD.v4 + RED.ADD.v2) -> no shared atomics, no stat smem, no flush.
// smem ~17KB -> 12 blocks x 3 warps = 36 warps/SM. Last-block finalize.
__global__ __launch_bounds__(TPB, BLOCKS_PER_SM)
void fused_stsim_kernel(const float4* __restrict__ X1,
                        const float4* __restrict__ X2,
                        const float*  __restrict__ Y,
                        const float*  __restrict__ W,
                        const int*    __restrict__ mask,
                        float* __restrict__ pred_out,   // may be null
                        float* __restrict__ coeff_out,  // may be null
                        int T, int numTiles)
{
    __shared__ float  sPart[2][ROWS * SLOTS];  // 2 x 8064 B
    __shared__ float  sW[D];                   // 328 B
    __shared__ __align__(16) float4 sW4[41];   // 656 B
    __shared__ unsigned isLast;

    const int tid = threadIdx.x;

    if (tid == 0) isLast = 0u;
    if (tid < D) sW[tid] = W[tid];
    __syncthreads();

    // 41-entry weight table: W pattern across 2 rows of float4s.
    if (tid < 41) {
        float4 w;
        if (tid < 20) {
            const int e = 4 * tid;
            w.x = sW[e]; w.y = sW[e + 1]; w.z = sW[e + 2]; w.w = sW[e + 3];
        } else if (tid == 20) {          // straddler: row els 80,81 | 0,1
            w.x = sW[80]; w.y = sW[81]; w.z = sW[0]; w.w = sW[1];
        } else {                          // q=21..40: next-row els 2..81
            const int e = 4 * (tid - 21) + 2;
            w.x = sW[e]; w.y = sW[e + 1]; w.z = sW[e + 2]; w.w = sW[e + 3];
        }
        sW4[tid] = w;
    }
    __syncthreads();

    // ---- stage helper: weighted partials of (X1-X2)^2 into sPart[buf] ----
#define STAGE(tileIdx, buf)                                                   \
    do {                                                                      \
        const int _row0 = (tileIdx) * ROWS;                                   \
        const int _rows = min(ROWS, T - _row0);                               \
        const int _n4   = (_rows * D) / 4;                                    \
        const float4* __restrict__ _A = X1 + (size_t)_row0 * D / 4;           \
        const float4* __restrict__ _B = X2 + (size_t)_row0 * D / 4;           \
        float* __restrict__ _S = sPart[buf];                                  \
        _Pragma("unroll 4")                                                   \
        for (int _i = tid; _i < _n4; _i += TPB) {                             \
            float4 _a = _A[_i];                                               \
            float4 _b = _B[_i];                                               \
            const int _p = _i / 41;                                           \
            const int _q = _i - _p * 41;                                      \
            float4 _w = sW4[_q];                                              \
            float _d0 = _a.x - _b.x, _d1 = _a.y - _b.y;                       \
            float _d2 = _a.z - _b.z, _d3 = _a.w - _b.w;                       \
            float _t0 = _d0 * _d0, _t1 = _d1 * _d1;                           \
            float _t2 = _d2 * _d2, _t3 = _d3 * _d3;                           \
            if (_q != 20) {                                                   \
                float _pa = fmaf(_t3, _w.w, fmaf(_t2, _w.z,                   \
                            fmaf(_t1, _w.y, _t0 * _w.x)));                    \
                const int _row  = 2 * _p + (_q > 20);                         \
                const int _slot = (_q < 20) ? _q : (_q - 20);                 \
                _S[_row * SLOTS + _slot] = _pa;                               \
            } else {                                                          \
                _S[(2 * _p) * SLOTS + 20]    = fmaf(_t1, _w.y, _t0 * _w.x);   \
                _S[(2 * _p + 1) * SLOTS + 0] = fmaf(_t3, _w.w, _t2 * _w.z);   \
            }                                                                 \
        }                                                                     \
    } while (0)

    const int firstTile = blockIdx.x;
    if (firstTile < numTiles) STAGE(firstTile, 0);   // prologue

    int k = 0;
    for (int tile = firstTile; tile < numTiles; tile += gridDim.x, k++) {
        const int cur  = k & 1;
        const int row0 = tile * ROWS;
        const int rows = min(ROWS, T - row0);
        const int t    = row0 + tid;

        __syncthreads();   // buf[cur] fully staged; prior reads of buf[cur^1] done

        // This tile's Y/mask loads issue early (overlap with staging below)
        float yReg = 0.0f; int gReg = 0;
        if (tid < rows) { yReg = Y[t]; gReg = mask[t]; }

        // Stage NEXT tile into the other buffer (LDGs go out first)
        const int nextTile = tile + gridDim.x;
        if (nextTile < numTiles) STAGE(nextTile, cur ^ 1);

        // Compute current tile: one row per thread; 21 conflict-free LDS.32
        if (tid < rows) {
            const float* __restrict__ pr = sPart[cur] + tid * SLOTS;
            float s0 = 0.0f, s1 = 0.0f, s2 = 0.0f;
            #pragma unroll
            for (int j = 0; j < 18; j += 3) {
                s0 += pr[j]; s1 += pr[j + 1]; s2 += pr[j + 2];
            }
            s0 += pr[18]; s1 += pr[19]; s2 += pr[20];
            const float s = s0 + s1 + s2;

            const float x = sqrtf(s);
            if (pred_out) pred_out[t] = x;

            // Two fire-and-forget vector global reductions (RED.ADD.v4/v2)
            const float y = yReg;
            float* gs = g_statsPad + (gReg << 5);
            atomicAdd(reinterpret_cast<float4*>(gs),
                      make_float4(1.0f, x, y, s));         // n, Sx, Sy, Sxx
            atomicAdd(reinterpret_cast<float2*>(gs + 4),
                      make_float2(y * y, x * y));          // Syy, Sxy
        }
    }
#undef STAGE

    // ---- last-block finalize ----
    __threadfence();   // order this block's REDs before the ticket
    __syncthreads();
    if (tid == 0) {
        if (atomicAdd(&g_ticket, 1u) == (unsigned)(gridDim.x - 1)) isLast = 1u;
    }
    __syncthreads();

    if (isLast) {
        double* red = reinterpret_cast<double*>(sPart[0]);  // dead buffer

        double acc = 0.0;
        for (int g = tid; g < NGROUP; g += TPB) {
            const float* gs = g_statsPad + (g << 5);
            const double n   = (double)__ldcg(gs + 0);
            const double Sx  = (double)__ldcg(gs + 1);
            const double Sy  = (double)__ldcg(gs + 2);
            const double Sxx = (double)__ldcg(gs + 3);
            const double Syy = (double)__ldcg(gs + 4);
            const double Sxy = (double)__ldcg(gs + 5);

            const double nom = Sxy - Sx * Sy / n;
            const double dx  = Sxx - Sx * Sx / n;
            const double dy  = Syy - Sy * Sy / n;
            acc += fabs(nom / sqrt(dx * dy));

            // Reset for the next launch/replay
            float* gw = g_statsPad + (g << 5);
            #pragma unroll
            for (int ss = 0; ss < 6; ss++) gw[ss] = 0.0f;
        }
        red[tid] = acc;
        __syncthreads();

        if (tid < 32) {
            double a = red[tid] + red[tid + 32] + red[tid + 64];
            #pragma unroll
            for (int ofs = 16; ofs > 0; ofs >>= 1)
                a += __shfl_down_sync(0xFFFFFFFFu, a, ofs);
            if (tid == 0) {
                if (coeff_out) coeff_out[0] = (float)(a / (double)NGROUP);
                g_ticket = 0;   // reset for next launch/replay
            }
        }
    }
}

extern "C" void kernel_launch(void* const* d_in, const int* in_sizes, int n_in,
                              void* d_out, int out_size)
{
    const float* X1   = (const float*)d_in[0];
    const float* X2   = (const float*)d_in[1];
    const float* Y    = (const float*)d_in[2];
    const float* W    = (const float*)d_in[3];
    const int*   mask = (const int*)  d_in[4];

    int T = in_sizes[0] / D;

    float* out = (float*)d_out;
    float* coeff_out = nullptr;
    float* pred_out  = nullptr;
    if (out_size == T + 1) {            // (coeff, pred) flattened in return order
        coeff_out = out;
        pred_out  = out + 1;
    } else if (out_size == T) {         // pred only
        pred_out  = out;
    } else {                            // coeff only
        coeff_out = out;
    }

    int numTiles = (T + ROWS - 1) / ROWS;
    int grid = numTiles < MAX_GRID ? numTiles : MAX_GRID;
    fused_stsim_kernel<<<grid, TPB>>>((const float4*)X1, (const float4*)X2,
                                      Y, W, mask, pred_out, coeff_out,
                                      T, numTiles);
}